// round 3
// baseline (speedup 1.0000x reference)
#include <cuda_runtime.h>
#include <math.h>

// Problem constants
#define BB 4
#define NN 8192
#define DD 1024
#define HH 16
#define DHH 64
#define GHH 256
#define ROWS (BB*HH)          // 64
#define NSPLIT 64

// ---------------- scratch (static device allocations only) ----------------
__device__ float g_part[NSPLIT * BB * DD];          // 1 MB
__device__ float g_xbar[BB * DD];
__device__ float g_barq[BB * DD];
__device__ float g_h1[ROWS * GHH];
__device__ float g_h2[ROWS * GHH];
__device__ float g_gbuf[ROWS * 2 * NN];             // 4 MB  (re | im)
__device__ float g_sbuf[ROWS * NN];                 // 2 MB
__device__ float g_vbuf[(size_t)BB * DD * NN];      // 128 MB, layout [b][c][n]

__device__ __forceinline__ float gelu_exact(float x) {
    return 0.5f * x * (1.0f + erff(x * 0.70710678118654752440f));
}

// ---------------- 1) xbar = mean_n x ----------------
__global__ void k_xbar_part(const float* __restrict__ x) {
    int s = blockIdx.x, b = blockIdx.y, tid = threadIdx.x;
    float acc[4] = {0.f, 0.f, 0.f, 0.f};
    const float* xp = x + ((size_t)b * NN + (size_t)s * (NN / NSPLIT)) * DD;
    for (int n = 0; n < NN / NSPLIT; n++) {
#pragma unroll
        for (int i = 0; i < 4; i++) acc[i] += xp[(size_t)n * DD + tid + 256 * i];
    }
#pragma unroll
    for (int i = 0; i < 4; i++)
        g_part[((size_t)s * BB + b) * DD + tid + 256 * i] = acc[i];
}

__global__ void k_xbar_red() {
    int b = blockIdx.x, tid = threadIdx.x;
    for (int d = tid; d < DD; d += 256) {
        float a = 0.f;
        for (int s = 0; s < NSPLIT; s++) a += g_part[((size_t)s * BB + b) * DD + d];
        g_xbar[b * DD + d] = a * (1.0f / NN);
    }
}

// ---------------- 2) bar_q = xbar @ w_q ----------------
__global__ void k_barq(const float* __restrict__ wq) {
    __shared__ float xb[DD];
    int b = blockIdx.y, tid = threadIdx.x;
    for (int l = tid; l < DD; l += 256) xb[l] = g_xbar[b * DD + l];
    __syncthreads();
    int c = blockIdx.x * 256 + tid;
    float acc = 0.f;
    for (int d = 0; d < DD; d++) acc += xb[d] * wq[(size_t)d * DD + c];
    g_barq[b * DD + c] = acc;
}

// ---------------- 3) LayerNorm + two tiny MLP first layers ----------------
__global__ void k_ln_mlp(const float* __restrict__ ln_g, const float* __restrict__ ln_b,
                         const float* __restrict__ gate_w1, const float* __restrict__ wrm_w1) {
    __shared__ float q[DHH];
    __shared__ float qn[DHH];
    __shared__ float stats[2];
    int r = blockIdx.x;               // r = b*H + h
    int b = r / HH, c0 = (r % HH) * DHH;
    int tid = threadIdx.x;
    if (tid < DHH) q[tid] = g_barq[b * DD + c0 + tid];
    __syncthreads();
    if (tid == 0) {
        float mu = 0.f;
        for (int i = 0; i < DHH; i++) mu += q[i];
        mu *= (1.0f / DHH);
        float var = 0.f;
        for (int i = 0; i < DHH; i++) { float t = q[i] - mu; var += t * t; }
        var *= (1.0f / DHH);
        stats[0] = mu; stats[1] = rsqrtf(var + 1e-5f);
    }
    __syncthreads();
    if (tid < DHH) qn[tid] = (q[tid] - stats[0]) * stats[1] * ln_g[tid] + ln_b[tid];
    __syncthreads();
    float a1 = 0.f, a2 = 0.f;
    for (int dh = 0; dh < DHH; dh++) {
        float qv = qn[dh];
        a1 += qv * gate_w1[dh * GHH + tid];
        a2 += qv * wrm_w1[dh * GHH + tid];
    }
    g_h1[r * GHH + tid] = gelu_exact(a1);
    g_h2[r * GHH + tid] = gelu_exact(a2);
}

// ---------------- 4) g = h1 @ gate_w2 ; s = h2 @ wrm_w2 ----------------
// grid.x = width/256 column tiles, grid.y = 4 row groups of 16
__global__ void k_gs(const float* __restrict__ w2, int width, int which) {
    __shared__ float sh[16][GHH];
    const float* hb = which ? g_h2 : g_h1;
    float* op = which ? g_sbuf : g_gbuf;
    int r0 = blockIdx.y * 16;
    int tid = threadIdx.x;
    for (int l = tid; l < 16 * GHH; l += 256)
        sh[l >> 8][l & 255] = hb[(r0 + (l >> 8)) * GHH + (l & 255)];
    __syncthreads();
    int c = blockIdx.x * 256 + tid;
    float acc[16];
#pragma unroll
    for (int r = 0; r < 16; r++) acc[r] = 0.f;
    for (int j = 0; j < GHH; j++) {
        float w = w2[(size_t)j * width + c];
#pragma unroll
        for (int r = 0; r < 16; r++) acc[r] += sh[r][j] * w;
    }
#pragma unroll
    for (int r = 0; r < 16; r++) op[(size_t)(r0 + r) * width + c] = acc[r];
}

// ---------------- 5) v = x @ w_v stored transposed: g_vbuf[b][c][n] ----------------
#define BM 128
#define BN 128
#define BK 16

__global__ __launch_bounds__(256, 2) void k_gemm_v(const float* __restrict__ x,
                                                   const float* __restrict__ wv) {
    __shared__ float As[BK][BM];        // As[k][c]
    __shared__ float Bs[BK][BN + 1];    // Bs[k][n]
    int b = blockIdx.z;
    int n0 = blockIdx.x * BN;
    int c0 = blockIdx.y * BM;
    int tid = threadIdx.x;
    int tx = tid & 15, ty = tid >> 4;
    const float* xb = x + (size_t)b * NN * DD;
    float acc[8][8];
#pragma unroll
    for (int i = 0; i < 8; i++)
#pragma unroll
        for (int j = 0; j < 8; j++) acc[i][j] = 0.f;

    for (int k0 = 0; k0 < DD; k0 += BK) {
#pragma unroll
        for (int i = 0; i < 2; i++) {
            int f = tid + 256 * i;
            int k = f >> 5, c4 = f & 31;
            float4 v4 = *(const float4*)(wv + (size_t)(k0 + k) * DD + c0 + c4 * 4);
            *(float4*)&As[k][c4 * 4] = v4;
        }
#pragma unroll
        for (int i = 0; i < 2; i++) {
            int f = tid + 256 * i;
            int n = f >> 2, k4 = f & 3;
            float4 v4 = *(const float4*)(xb + (size_t)(n0 + n) * DD + k0 + k4 * 4);
            Bs[k4 * 4 + 0][n] = v4.x;
            Bs[k4 * 4 + 1][n] = v4.y;
            Bs[k4 * 4 + 2][n] = v4.z;
            Bs[k4 * 4 + 3][n] = v4.w;
        }
        __syncthreads();
#pragma unroll
        for (int k = 0; k < BK; k++) {
            float a[8], bbv[8];
#pragma unroll
            for (int i = 0; i < 8; i++) a[i] = As[k][ty + 16 * i];
#pragma unroll
            for (int j = 0; j < 8; j++) bbv[j] = Bs[k][tx + 16 * j];
#pragma unroll
            for (int i = 0; i < 8; i++)
#pragma unroll
                for (int j = 0; j < 8; j++) acc[i][j] += a[i] * bbv[j];
        }
        __syncthreads();
    }
#pragma unroll
    for (int i = 0; i < 8; i++) {
        int c = c0 + ty + 16 * i;
        float* orow = g_vbuf + ((size_t)b * DD + c) * NN + n0;
#pragma unroll
        for (int j = 0; j < 8; j++) orow[tx + 16 * j] = acc[i][j];
    }
}

// ---------------- 6) FFT -> *g -> IFFT -> fused butterfly/scale/residual ----------------
// one CTA per sequence (b, c=h*64+dh); 8192-pt radix-2, in place in smem.
__global__ void k_fft() {
    extern __shared__ float2 sm[];
    float2* d = sm;              // 8192 complex
    float2* tw = sm + 8192;      // 4096 twiddles: tw[t] = exp(-i*pi*t/4096)
    int tid = threadIdx.x;
    int seq = blockIdx.x;
    int row = seq >> 6;          // = b*H + h
    float* base = g_vbuf + (size_t)seq * NN;

    for (int t = tid; t < 4096; t += 256) {
        float sv, cv;
        sincospif(t * (1.0f / 4096.0f), &sv, &cv);
        tw[t] = make_float2(cv, -sv);
    }
    for (int n = tid; n < NN; n += 256) d[n] = make_float2(base[n], 0.f);
    __syncthreads();

    // forward DIF (natural -> bit-reversed)
    int shift = 0;
    for (int m = 4096; m >= 1; m >>= 1) {
        for (int idx = tid; idx < 4096; idx += 256) {
            int j = idx & (m - 1);
            int bas = ((idx - j) << 1) + j;
            float2 a = d[bas];
            float2 b2 = d[bas + m];
            float2 w = tw[j << shift];
            float dx = a.x - b2.x, dy = a.y - b2.y;
            d[bas] = make_float2(a.x + b2.x, a.y + b2.y);
            d[bas + m] = make_float2(dx * w.x - dy * w.y, dx * w.y + dy * w.x);
        }
        shift++;
        __syncthreads();
    }

    // pointwise multiply by g (indexed in bit-reversed order)
    const float* gre = g_gbuf + (size_t)row * (2 * NN);
    const float* gim = gre + NN;
    for (int p = tid; p < NN; p += 256) {
        int k = __brev((unsigned)p) >> 19;
        float2 a = d[p];
        float gr = gre[k], gi = gim[k];
        d[p] = make_float2(a.x * gr - a.y * gi, a.x * gi + a.y * gr);
    }
    __syncthreads();

    // inverse DIT (bit-reversed -> natural), conj twiddles
    shift = 12;
    for (int m = 1; m <= 4096; m <<= 1) {
        for (int idx = tid; idx < 4096; idx += 256) {
            int j = idx & (m - 1);
            int bas = ((idx - j) << 1) + j;
            float2 a = d[bas];
            float2 b2 = d[bas + m];
            float2 w = tw[j << shift];   // use conj(w)
            float tx2 = b2.x * w.x + b2.y * w.y;
            float ty2 = b2.y * w.x - b2.x * w.y;
            d[bas] = make_float2(a.x + tx2, a.y + ty2);
            d[bas + m] = make_float2(a.x - tx2, a.y - ty2);
        }
        shift--;
        __syncthreads();
    }

    // fused: v_tilde = real/N ; even/odd hadamard, scale by s, inverse hadamard, add
    const float* srow = g_sbuf + (size_t)row * NN;
    const float inv = 1.0f / (float)NN;
    for (int k = tid; k < NN / 2; k += 256) {
        float e = d[2 * k].x * inv;
        float o = d[2 * k + 1].x * inv;
        float s0 = srow[k];
        float s1 = srow[NN / 2 + k];
        float su = e + o, df = e - o;
        float p = s0 * su, q = s1 * df;
        base[2 * k] = e + 0.5f * (p + q);
        base[2 * k + 1] = o + 0.5f * (p - q);
    }
}

// ---------------- 7) out = y @ w_o (y = g_vbuf^T per batch) ----------------
__global__ __launch_bounds__(256, 2) void k_gemm_o(const float* __restrict__ wo,
                                                   float* __restrict__ outp) {
    __shared__ float As[BK][BM];   // As[k][m] (m = token n)
    __shared__ float Bs[BK][BN];   // Bs[k][c']
    int b = blockIdx.z;
    int m0 = blockIdx.x * BM;
    int c0 = blockIdx.y * BN;
    int tid = threadIdx.x;
    int tx = tid & 15, ty = tid >> 4;
    const float* ab = g_vbuf + (size_t)b * DD * NN;
    float acc[8][8];
#pragma unroll
    for (int i = 0; i < 8; i++)
#pragma unroll
        for (int j = 0; j < 8; j++) acc[i][j] = 0.f;

    for (int k0 = 0; k0 < DD; k0 += BK) {
#pragma unroll
        for (int i = 0; i < 2; i++) {
            int f = tid + 256 * i;
            int k = f >> 5, m4 = f & 31;
            *(float4*)&As[k][m4 * 4] = *(const float4*)(ab + (size_t)(k0 + k) * NN + m0 + m4 * 4);
            *(float4*)&Bs[k][m4 * 4] = *(const float4*)(wo + (size_t)(k0 + k) * DD + c0 + m4 * 4);
        }
        __syncthreads();
#pragma unroll
        for (int k = 0; k < BK; k++) {
            float a[8], bbv[8];
#pragma unroll
            for (int i = 0; i < 8; i++) a[i] = As[k][ty + 16 * i];
#pragma unroll
            for (int j = 0; j < 8; j++) bbv[j] = Bs[k][tx + 16 * j];
#pragma unroll
            for (int i = 0; i < 8; i++)
#pragma unroll
                for (int j = 0; j < 8; j++) acc[i][j] += a[i] * bbv[j];
        }
        __syncthreads();
    }
#pragma unroll
    for (int i = 0; i < 8; i++) {
        int m = m0 + ty + 16 * i;
        float* orow = outp + ((size_t)b * NN + m) * DD + c0;
#pragma unroll
        for (int j = 0; j < 8; j++) orow[tx + 16 * j] = acc[i][j];
    }
}

// ---------------- launch ----------------
extern "C" void kernel_launch(void* const* d_in, const int* in_sizes, int n_in,
                              void* d_out, int out_size) {
    const float* x       = (const float*)d_in[0];
    const float* w_q     = (const float*)d_in[1];
    const float* w_v     = (const float*)d_in[2];
    const float* w_o     = (const float*)d_in[3];
    const float* ln_g    = (const float*)d_in[4];
    const float* ln_b    = (const float*)d_in[5];
    const float* gate_w1 = (const float*)d_in[6];
    const float* gate_w2 = (const float*)d_in[7];
    const float* wrm_w1  = (const float*)d_in[8];
    const float* wrm_w2  = (const float*)d_in[9];
    float* outp = (float*)d_out;

    cudaFuncSetAttribute(k_fft, cudaFuncAttributeMaxDynamicSharedMemorySize, 96 * 1024);

    k_xbar_part<<<dim3(NSPLIT, BB), 256>>>(x);
    k_xbar_red<<<BB, 256>>>();
    k_barq<<<dim3(DD / 256, BB), 256>>>(w_q);
    k_ln_mlp<<<ROWS, 256>>>(ln_g, ln_b, gate_w1, wrm_w1);
    k_gs<<<dim3(2 * NN / 256, 4), 256>>>(gate_w2, 2 * NN, 0);
    k_gs<<<dim3(NN / 256, 4), 256>>>(wrm_w2, NN, 1);
    k_gemm_v<<<dim3(NN / BN, DD / BM, BB), 256>>>(x, w_v);
    k_fft<<<BB * DD, 256, 96 * 1024>>>();
    k_gemm_o<<<dim3(NN / BM, DD / BN, BB), 256>>>(w_o, outp);
}

// round 4
// speedup vs baseline: 1.3122x; 1.3122x over previous
#include <cuda_runtime.h>
#include <mma.h>
#include <math.h>

using namespace nvcuda;

// Problem constants
#define BB 4
#define NN 8192
#define DD 1024
#define HH 16
#define DHH 64
#define GHH 256
#define ROWS (BB*HH)          // 64
#define NSPLIT 64

// ---------------- scratch (static device allocations only) ----------------
__device__ float g_part[NSPLIT * BB * DD];          // 1 MB
__device__ float g_xbar[BB * DD];
__device__ float g_barq[BB * DD];
__device__ float g_h1[ROWS * GHH];
__device__ float g_h2[ROWS * GHH];
__device__ float g_gbuf[ROWS * 2 * NN];             // 4 MB  (re | im)
__device__ float g_sbuf[ROWS * NN];                 // 2 MB
__device__ float g_vbuf[(size_t)BB * DD * NN];      // 128 MB, layout [b][c][n]

__device__ __forceinline__ float gelu_exact(float x) {
    return 0.5f * x * (1.0f + erff(x * 0.70710678118654752440f));
}

// ---------------- 1) xbar = mean_n x ----------------
__global__ void k_xbar_part(const float* __restrict__ x) {
    int s = blockIdx.x, b = blockIdx.y, tid = threadIdx.x;
    float acc[4] = {0.f, 0.f, 0.f, 0.f};
    const float* xp = x + ((size_t)b * NN + (size_t)s * (NN / NSPLIT)) * DD;
    for (int n = 0; n < NN / NSPLIT; n++) {
#pragma unroll
        for (int i = 0; i < 4; i++) acc[i] += xp[(size_t)n * DD + tid + 256 * i];
    }
#pragma unroll
    for (int i = 0; i < 4; i++)
        g_part[((size_t)s * BB + b) * DD + tid + 256 * i] = acc[i];
}

__global__ void k_xbar_red() {
    int b = blockIdx.x, tid = threadIdx.x;
    for (int d = tid; d < DD; d += 256) {
        float a = 0.f;
        for (int s = 0; s < NSPLIT; s++) a += g_part[((size_t)s * BB + b) * DD + d];
        g_xbar[b * DD + d] = a * (1.0f / NN);
    }
}

// ---------------- 2) bar_q = xbar @ w_q ----------------
__global__ void k_barq(const float* __restrict__ wq) {
    __shared__ float xb[DD];
    int b = blockIdx.y, tid = threadIdx.x;
    for (int l = tid; l < DD; l += 256) xb[l] = g_xbar[b * DD + l];
    __syncthreads();
    int c = blockIdx.x * 256 + tid;
    float acc = 0.f;
    for (int d = 0; d < DD; d++) acc += xb[d] * wq[(size_t)d * DD + c];
    g_barq[b * DD + c] = acc;
}

// ---------------- 3) LayerNorm + two tiny MLP first layers ----------------
__global__ void k_ln_mlp(const float* __restrict__ ln_g, const float* __restrict__ ln_b,
                         const float* __restrict__ gate_w1, const float* __restrict__ wrm_w1) {
    __shared__ float q[DHH];
    __shared__ float qn[DHH];
    __shared__ float stats[2];
    int r = blockIdx.x;               // r = b*H + h
    int b = r / HH, c0 = (r % HH) * DHH;
    int tid = threadIdx.x;
    if (tid < DHH) q[tid] = g_barq[b * DD + c0 + tid];
    __syncthreads();
    if (tid == 0) {
        float mu = 0.f;
        for (int i = 0; i < DHH; i++) mu += q[i];
        mu *= (1.0f / DHH);
        float var = 0.f;
        for (int i = 0; i < DHH; i++) { float t = q[i] - mu; var += t * t; }
        var *= (1.0f / DHH);
        stats[0] = mu; stats[1] = rsqrtf(var + 1e-5f);
    }
    __syncthreads();
    if (tid < DHH) qn[tid] = (q[tid] - stats[0]) * stats[1] * ln_g[tid] + ln_b[tid];
    __syncthreads();
    float a1 = 0.f, a2 = 0.f;
    for (int dh = 0; dh < DHH; dh++) {
        float qv = qn[dh];
        a1 += qv * gate_w1[dh * GHH + tid];
        a2 += qv * wrm_w1[dh * GHH + tid];
    }
    g_h1[r * GHH + tid] = gelu_exact(a1);
    g_h2[r * GHH + tid] = gelu_exact(a2);
}

// ---------------- 4) g = h1 @ gate_w2 ; s = h2 @ wrm_w2 ----------------
__global__ void k_gs(const float* __restrict__ w2, int width, int which) {
    __shared__ float sh[16][GHH];
    const float* hb = which ? g_h2 : g_h1;
    float* op = which ? g_sbuf : g_gbuf;
    int r0 = blockIdx.y * 16;
    int tid = threadIdx.x;
    for (int l = tid; l < 16 * GHH; l += 256)
        sh[l >> 8][l & 255] = hb[(r0 + (l >> 8)) * GHH + (l & 255)];
    __syncthreads();
    int c = blockIdx.x * 256 + tid;
    float acc[16];
#pragma unroll
    for (int r = 0; r < 16; r++) acc[r] = 0.f;
    for (int j = 0; j < GHH; j++) {
        float w = w2[(size_t)j * width + c];
#pragma unroll
        for (int r = 0; r < 16; r++) acc[r] += sh[r][j] * w;
    }
#pragma unroll
    for (int r = 0; r < 16; r++) op[(size_t)(r0 + r) * width + c] = acc[r];
}

// ================= tf32 tensor-core GEMMs =================
// Tile: 128(BMx) x 128(BNx) x 16(BKx). 8 warps in 2x4; warp tile 64x32.
#define BMX 128
#define BNX 128
#define BKX 16
#define LDA 132   // padded leading dims (multiple of 4)
#define LDB 20

// ---------------- 5) v = x @ w_v stored transposed: g_vbuf[b][c][n] ----------------
// C[c][n] = sum_d wv[d][c] * x[n][d]
// A col-major (ld=DD over d): wv[d*DD + c];  B col-major (ld=DD over n): x[n*DD + d]
__global__ __launch_bounds__(256) void k_gemm_v_tc(const float* __restrict__ x,
                                                   const float* __restrict__ wv) {
    __shared__ __align__(16) float As[BKX * LDA];   // col-major: As[d*LDA + c]
    __shared__ __align__(16) float Bs[BNX * LDB];   // col-major: Bs[n*LDB + d]
    int b = blockIdx.z;
    int c0 = blockIdx.x * BMX;     // c-tile fastest -> 8 CTAs share one x block in L2
    int n0 = blockIdx.y * BNX;
    int tid = threadIdx.x;
    int warp = tid >> 5;
    int wm = (warp & 1) * 64;      // c offset within tile
    int wn = (warp >> 1) * 32;     // n offset within tile
    const float* xb = x + (size_t)b * NN * DD;

    wmma::fragment<wmma::accumulator, 16, 16, 8, float> acc[4][2];
#pragma unroll
    for (int i = 0; i < 4; i++)
#pragma unroll
        for (int j = 0; j < 2; j++) wmma::fill_fragment(acc[i][j], 0.0f);

    for (int k0 = 0; k0 < DD; k0 += BKX) {
        // load A tile: 16 d-rows x 128 c (contiguous in c)
#pragma unroll
        for (int i = 0; i < 2; i++) {
            int f = tid + 256 * i;           // 0..511
            int d = f >> 5, c4 = f & 31;
            *(float4*)&As[d * LDA + c4 * 4] =
                *(const float4*)(wv + (size_t)(k0 + d) * DD + c0 + c4 * 4);
        }
        // load B tile: 128 n-cols x 16 d (contiguous in d)
#pragma unroll
        for (int i = 0; i < 2; i++) {
            int f = tid + 256 * i;
            int n = f >> 2, k4 = f & 3;
            *(float4*)&Bs[n * LDB + k4 * 4] =
                *(const float4*)(xb + (size_t)(n0 + n) * DD + k0 + k4 * 4);
        }
        __syncthreads();
#pragma unroll
        for (int kk = 0; kk < BKX; kk += 8) {
            wmma::fragment<wmma::matrix_a, 16, 16, 8, wmma::precision::tf32, wmma::col_major> af[4];
            wmma::fragment<wmma::matrix_b, 16, 16, 8, wmma::precision::tf32, wmma::col_major> bf[2];
#pragma unroll
            for (int i = 0; i < 4; i++) {
                wmma::load_matrix_sync(af[i], As + kk * LDA + wm + 16 * i, LDA);
#pragma unroll
                for (int t = 0; t < af[i].num_elements; t++)
                    af[i].x[t] = wmma::__float_to_tf32(af[i].x[t]);
            }
#pragma unroll
            for (int j = 0; j < 2; j++) {
                wmma::load_matrix_sync(bf[j], Bs + (wn + 16 * j) * LDB + kk, LDB);
#pragma unroll
                for (int t = 0; t < bf[j].num_elements; t++)
                    bf[j].x[t] = wmma::__float_to_tf32(bf[j].x[t]);
            }
#pragma unroll
            for (int i = 0; i < 4; i++)
#pragma unroll
                for (int j = 0; j < 2; j++)
                    wmma::mma_sync(acc[i][j], af[i], bf[j], acc[i][j]);
        }
        __syncthreads();
    }
    // store: g_vbuf[b][c][n], row-major ld = NN
#pragma unroll
    for (int i = 0; i < 4; i++)
#pragma unroll
        for (int j = 0; j < 2; j++) {
            float* cp = g_vbuf + ((size_t)b * DD + c0 + wm + 16 * i) * NN + n0 + wn + 16 * j;
            wmma::store_matrix_sync(cp, acc[i][j], NN, wmma::mem_row_major);
        }
}

// ---------------- 7) out = y @ w_o  (y[b][m][d] = g_vbuf[b][d][m]) ----------------
// C[m][c'] = sum_d vbuf[d][m] * wo[d][c']
// A col-major (ld=NN): vbuf[d*NN + m];  B row-major (ld=DD): wo[d*DD + c']
__global__ __launch_bounds__(256) void k_gemm_o_tc(const float* __restrict__ wo,
                                                   float* __restrict__ outp) {
    __shared__ __align__(16) float As[BKX * LDA];   // col-major: As[d*LDA + m]
    __shared__ __align__(16) float Bs[BKX * LDA];   // row-major: Bs[d*LDA + c]
    int b = blockIdx.z;
    int c0 = blockIdx.x * BNX;     // c'-tile fastest -> share vbuf m-block in L2
    int m0 = blockIdx.y * BMX;
    int tid = threadIdx.x;
    int warp = tid >> 5;
    int wm = (warp & 1) * 64;      // m offset
    int wn = (warp >> 1) * 32;     // c' offset
    const float* ab = g_vbuf + (size_t)b * DD * NN;

    wmma::fragment<wmma::accumulator, 16, 16, 8, float> acc[4][2];
#pragma unroll
    for (int i = 0; i < 4; i++)
#pragma unroll
        for (int j = 0; j < 2; j++) wmma::fill_fragment(acc[i][j], 0.0f);

    for (int k0 = 0; k0 < DD; k0 += BKX) {
#pragma unroll
        for (int i = 0; i < 2; i++) {
            int f = tid + 256 * i;
            int d = f >> 5, m4 = f & 31;
            *(float4*)&As[d * LDA + m4 * 4] =
                *(const float4*)(ab + (size_t)(k0 + d) * NN + m0 + m4 * 4);
            *(float4*)&Bs[d * LDA + m4 * 4] =
                *(const float4*)(wo + (size_t)(k0 + d) * DD + c0 + m4 * 4);
        }
        __syncthreads();
#pragma unroll
        for (int kk = 0; kk < BKX; kk += 8) {
            wmma::fragment<wmma::matrix_a, 16, 16, 8, wmma::precision::tf32, wmma::col_major> af[4];
            wmma::fragment<wmma::matrix_b, 16, 16, 8, wmma::precision::tf32, wmma::row_major> bf[2];
#pragma unroll
            for (int i = 0; i < 4; i++) {
                wmma::load_matrix_sync(af[i], As + kk * LDA + wm + 16 * i, LDA);
#pragma unroll
                for (int t = 0; t < af[i].num_elements; t++)
                    af[i].x[t] = wmma::__float_to_tf32(af[i].x[t]);
            }
#pragma unroll
            for (int j = 0; j < 2; j++) {
                wmma::load_matrix_sync(bf[j], Bs + kk * LDA + wn + 16 * j, LDA);
#pragma unroll
                for (int t = 0; t < bf[j].num_elements; t++)
                    bf[j].x[t] = wmma::__float_to_tf32(bf[j].x[t]);
            }
#pragma unroll
            for (int i = 0; i < 4; i++)
#pragma unroll
                for (int j = 0; j < 2; j++)
                    wmma::mma_sync(acc[i][j], af[i], bf[j], acc[i][j]);
        }
        __syncthreads();
    }
#pragma unroll
    for (int i = 0; i < 4; i++)
#pragma unroll
        for (int j = 0; j < 2; j++) {
            float* cp = outp + ((size_t)b * NN + m0 + wm + 16 * i) * DD + c0 + wn + 16 * j;
            wmma::store_matrix_sync(cp, acc[i][j], DD, wmma::mem_row_major);
        }
}

// ---------------- 6) FFT -> *g -> IFFT -> fused butterfly/scale/residual ----------------
__global__ void k_fft() {
    extern __shared__ float2 sm[];
    float2* d = sm;              // 8192 complex
    float2* tw = sm + 8192;      // 4096 twiddles: tw[t] = exp(-i*pi*t/4096)
    int tid = threadIdx.x;
    int seq = blockIdx.x;
    int row = seq >> 6;          // = b*H + h
    float* base = g_vbuf + (size_t)seq * NN;

    for (int t = tid; t < 4096; t += 256) {
        float sv, cv;
        sincospif(t * (1.0f / 4096.0f), &sv, &cv);
        tw[t] = make_float2(cv, -sv);
    }
    for (int n = tid; n < NN; n += 256) d[n] = make_float2(base[n], 0.f);
    __syncthreads();

    // forward DIF (natural -> bit-reversed)
    int shift = 0;
    for (int m = 4096; m >= 1; m >>= 1) {
        for (int idx = tid; idx < 4096; idx += 256) {
            int j = idx & (m - 1);
            int bas = ((idx - j) << 1) + j;
            float2 a = d[bas];
            float2 b2 = d[bas + m];
            float2 w = tw[j << shift];
            float dx = a.x - b2.x, dy = a.y - b2.y;
            d[bas] = make_float2(a.x + b2.x, a.y + b2.y);
            d[bas + m] = make_float2(dx * w.x - dy * w.y, dx * w.y + dy * w.x);
        }
        shift++;
        __syncthreads();
    }

    // pointwise multiply by g (indexed in bit-reversed order)
    const float* gre = g_gbuf + (size_t)row * (2 * NN);
    const float* gim = gre + NN;
    for (int p = tid; p < NN; p += 256) {
        int k = __brev((unsigned)p) >> 19;
        float2 a = d[p];
        float gr = gre[k], gi = gim[k];
        d[p] = make_float2(a.x * gr - a.y * gi, a.x * gi + a.y * gr);
    }
    __syncthreads();

    // inverse DIT (bit-reversed -> natural), conj twiddles
    shift = 12;
    for (int m = 1; m <= 4096; m <<= 1) {
        for (int idx = tid; idx < 4096; idx += 256) {
            int j = idx & (m - 1);
            int bas = ((idx - j) << 1) + j;
            float2 a = d[bas];
            float2 b2 = d[bas + m];
            float2 w = tw[j << shift];   // conj(w)
            float tx2 = b2.x * w.x + b2.y * w.y;
            float ty2 = b2.y * w.x - b2.x * w.y;
            d[bas] = make_float2(a.x + tx2, a.y + ty2);
            d[bas + m] = make_float2(a.x - tx2, a.y - ty2);
        }
        shift--;
        __syncthreads();
    }

    // fused: v_tilde = real/N ; even/odd hadamard, scale by s, inverse hadamard, add
    const float* srow = g_sbuf + (size_t)row * NN;
    const float inv = 1.0f / (float)NN;
    for (int k = tid; k < NN / 2; k += 256) {
        float e = d[2 * k].x * inv;
        float o = d[2 * k + 1].x * inv;
        float s0 = srow[k];
        float s1 = srow[NN / 2 + k];
        float su = e + o, df = e - o;
        float p = s0 * su, q = s1 * df;
        base[2 * k] = e + 0.5f * (p + q);
        base[2 * k + 1] = o + 0.5f * (p - q);
    }
}

// ---------------- launch ----------------
extern "C" void kernel_launch(void* const* d_in, const int* in_sizes, int n_in,
                              void* d_out, int out_size) {
    const float* x       = (const float*)d_in[0];
    const float* w_q     = (const float*)d_in[1];
    const float* w_v     = (const float*)d_in[2];
    const float* w_o     = (const float*)d_in[3];
    const float* ln_g    = (const float*)d_in[4];
    const float* ln_b    = (const float*)d_in[5];
    const float* gate_w1 = (const float*)d_in[6];
    const float* gate_w2 = (const float*)d_in[7];
    const float* wrm_w1  = (const float*)d_in[8];
    const float* wrm_w2  = (const float*)d_in[9];
    float* outp = (float*)d_out;

    cudaFuncSetAttribute(k_fft, cudaFuncAttributeMaxDynamicSharedMemorySize, 96 * 1024);

    k_xbar_part<<<dim3(NSPLIT, BB), 256>>>(x);
    k_xbar_red<<<BB, 256>>>();
    k_barq<<<dim3(DD / 256, BB), 256>>>(w_q);
    k_ln_mlp<<<ROWS, 256>>>(ln_g, ln_b, gate_w1, wrm_w1);
    k_gs<<<dim3(2 * NN / 256, 4), 256>>>(gate_w2, 2 * NN, 0);
    k_gs<<<dim3(NN / 256, 4), 256>>>(wrm_w2, NN, 1);
    k_gemm_v_tc<<<dim3(DD / BMX, NN / BNX, BB), 256>>>(x, w_v);
    k_fft<<<BB * DD, 256, 96 * 1024>>>();
    k_gemm_o_tc<<<dim3(DD / BNX, NN / BMX, BB), 256>>>(w_o, outp);
}